// round 3
// baseline (speedup 1.0000x reference)
#include <cuda_runtime.h>

typedef unsigned long long ull;

#define F       128
#define NB      3
#define P       32      // points per block
#define THREADS 256
#define OMEGA   30.0f

// Pre-transposed + permuted weights: g_wt[layer][i*F + perm(j)] = W[j][i]
// layer = b*2 + (0:w1, 1:w2). perm(j) groups j so that thread jg's 8 features
// load as two conflict-free float4s at words jg*4 and 64+jg*4.
__device__ __align__(16) float g_wt[6 * F * F];

__device__ __forceinline__ int perm_j(int j) {
    return ((j & 4) << 4) | ((j >> 3) << 2) | (j & 3);
}

__device__ __forceinline__ ull dup2(float w) {
    ull r; asm("mov.b64 %0, {%1, %1};" : "=l"(r) : "f"(w)); return r;
}
__device__ __forceinline__ float2 unpack2(ull v) {
    float2 r; asm("mov.b64 {%0, %1}, %2;" : "=f"(r.x), "=f"(r.y) : "l"(v)); return r;
}
__device__ __forceinline__ ull ffma2(ull a, ull b, ull c) {
    ull d; asm("fma.rn.f32x2 %0, %1, %2, %3;" : "=l"(d) : "l"(a), "l"(b), "l"(c)); return d;
}

// ---------------- weight transpose pre-kernel ----------------
__global__ void transpose_weights_kernel(const float* __restrict__ res_w1,
                                         const float* __restrict__ res_w2) {
    int t = blockIdx.x * blockDim.x + threadIdx.x;
    if (t >= 6 * F * F) return;
    int layer = t >> 14;            // / (F*F)
    int e     = t & (F * F - 1);
    int j     = e >> 7;
    int i     = e & (F - 1);        // consecutive t -> consecutive i (coalesced read)
    int b     = layer >> 1;
    const float* src = (layer & 1) ? (res_w2 + b * F * F) : (res_w1 + b * F * F);
    g_wt[layer * F * F + i * F + perm_j(j)] = src[j * F + i];
}

// ---------------- main kernel helpers ----------------

// Copy one pre-transposed weight matrix (64KB) into shared. Coalesced, conflict-free.
__device__ __forceinline__ void stage(const float* __restrict__ gsrc,
                                      float* __restrict__ Wsm, int tid) {
    const float4* s4 = reinterpret_cast<const float4*>(gsrc);
    float4* d4 = reinterpret_cast<float4*>(Wsm);
#pragma unroll
    for (int t = tid; t < (F * F) / 4; t += THREADS)
        d4[t] = __ldg(s4 + t);
}

// acc[c][v] (float2 over 2 points) = sum_i W[j=8*jg+c][i] * X[v][i][2*pg + {0,1}]
// X2 layout: float2 row (v*F + i) has 16 float2 entries, swizzled: entry
// (p-pair q) stored at q ^ ((i>>3)&15).
__device__ __forceinline__ void matmul(const float* __restrict__ Wsm,
                                       const float2* __restrict__ X2,
                                       int jg, int pg, ull acc[8][4]) {
#pragma unroll
    for (int c = 0; c < 8; c++)
#pragma unroll
        for (int v = 0; v < 4; v++) acc[c][v] = 0ull;

    const float* wp = Wsm + jg * 4;
#pragma unroll 4
    for (int i = 0; i < F; i++) {
        const float4 wa = *reinterpret_cast<const float4*>(wp + i * F);
        const float4 wb = *reinterpret_cast<const float4*>(wp + i * F + 64);
        const int xoff = i * 16 + (pg ^ ((i >> 3) & 15));
        const ull x0 = *reinterpret_cast<const ull*>(X2 + xoff);
        const ull x1 = *reinterpret_cast<const ull*>(X2 + 2048 + xoff);
        const ull x2 = *reinterpret_cast<const ull*>(X2 + 4096 + xoff);
        const ull x3 = *reinterpret_cast<const ull*>(X2 + 6144 + xoff);
        ull w;
        w = dup2(wa.x);
        acc[0][0] = ffma2(w, x0, acc[0][0]); acc[0][1] = ffma2(w, x1, acc[0][1]);
        acc[0][2] = ffma2(w, x2, acc[0][2]); acc[0][3] = ffma2(w, x3, acc[0][3]);
        w = dup2(wa.y);
        acc[1][0] = ffma2(w, x0, acc[1][0]); acc[1][1] = ffma2(w, x1, acc[1][1]);
        acc[1][2] = ffma2(w, x2, acc[1][2]); acc[1][3] = ffma2(w, x3, acc[1][3]);
        w = dup2(wa.z);
        acc[2][0] = ffma2(w, x0, acc[2][0]); acc[2][1] = ffma2(w, x1, acc[2][1]);
        acc[2][2] = ffma2(w, x2, acc[2][2]); acc[2][3] = ffma2(w, x3, acc[2][3]);
        w = dup2(wa.w);
        acc[3][0] = ffma2(w, x0, acc[3][0]); acc[3][1] = ffma2(w, x1, acc[3][1]);
        acc[3][2] = ffma2(w, x2, acc[3][2]); acc[3][3] = ffma2(w, x3, acc[3][3]);
        w = dup2(wb.x);
        acc[4][0] = ffma2(w, x0, acc[4][0]); acc[4][1] = ffma2(w, x1, acc[4][1]);
        acc[4][2] = ffma2(w, x2, acc[4][2]); acc[4][3] = ffma2(w, x3, acc[4][3]);
        w = dup2(wb.y);
        acc[5][0] = ffma2(w, x0, acc[5][0]); acc[5][1] = ffma2(w, x1, acc[5][1]);
        acc[5][2] = ffma2(w, x2, acc[5][2]); acc[5][3] = ffma2(w, x3, acc[5][3]);
        w = dup2(wb.z);
        acc[6][0] = ffma2(w, x0, acc[6][0]); acc[6][1] = ffma2(w, x1, acc[6][1]);
        acc[6][2] = ffma2(w, x2, acc[6][2]); acc[6][3] = ffma2(w, x3, acc[6][3]);
        w = dup2(wb.w);
        acc[7][0] = ffma2(w, x0, acc[7][0]); acc[7][1] = ffma2(w, x1, acc[7][1]);
        acc[7][2] = ffma2(w, x2, acc[7][2]); acc[7][3] = ffma2(w, x3, acc[7][3]);
    }
}

__global__ void __launch_bounds__(THREADS, 1)
fsrn_kernel(const float* __restrict__ coords,
            const float* __restrict__ first_w, const float* __restrict__ first_b,
            const float* __restrict__ res_b1,  const float* __restrict__ res_b2,
            const float* __restrict__ final_w,
            float* __restrict__ out) {
    extern __shared__ float smem[];
    float*  Wsm = smem;                               // F*F floats (64KB)
    float2* S2  = reinterpret_cast<float2*>(smem + F * F);   // 4*F rows x 16 float2
    float2* B2  = S2 + 4 * F * 16;                            // same size

    const int tid = threadIdx.x;
    const int jg  = tid & 15;       // 16 feature groups, Jt=8 features each
    const int pg  = tid >> 4;       // 16 point-pair groups, Pt=2 points each
    const int po  = pg ^ jg;        // swizzled float2 offset for rows j in this jg
    const int blockBase = blockIdx.x * P;

    // ---- first layer: h = sin(omega*(fw@c + fb)); dh_k = omega*cos(..)*fw[:,k]
    {
        const int p0 = (blockBase + 2 * pg) * 3;
        const float c0x = __ldg(coords + p0 + 0);
        const float c0y = __ldg(coords + p0 + 1);
        const float c0z = __ldg(coords + p0 + 2);
        const float c1x = __ldg(coords + p0 + 3);
        const float c1y = __ldg(coords + p0 + 4);
        const float c1z = __ldg(coords + p0 + 5);
#pragma unroll
        for (int c = 0; c < 8; c++) {
            const int j = jg * 8 + c;
            const float f0 = __ldg(first_w + j * 3 + 0);
            const float f1 = __ldg(first_w + j * 3 + 1);
            const float f2 = __ldg(first_w + j * 3 + 2);
            const float fb = __ldg(first_b + j);
            float za = fmaf(f0, c0x, fmaf(f1, c0y, fmaf(f2, c0z, fb)));
            float zb = fmaf(f0, c1x, fmaf(f1, c1y, fmaf(f2, c1z, fb)));
            float sa, ca, sb, cb;
            __sincosf(OMEGA * za, &sa, &ca);
            __sincosf(OMEGA * zb, &sb, &cb);
            float ga = OMEGA * ca, gb = OMEGA * cb;
            S2[(0 * F + j) * 16 + po] = make_float2(sa, sb);
            S2[(1 * F + j) * 16 + po] = make_float2(ga * f0, gb * f0);
            S2[(2 * F + j) * 16 + po] = make_float2(ga * f1, gb * f1);
            S2[(3 * F + j) * 16 + po] = make_float2(ga * f2, gb * f2);
        }
    }

    // ---- residual blocks
    ull acc[8][4];
    for (int b = 0; b < NB; b++) {
        const float s = (b == 0) ? 1.0f : 0.5f;

        __syncthreads();                       // S2 writes visible; Wsm free
        stage(g_wt + (2 * b) * F * F, Wsm, tid);
        __syncthreads();

        matmul(Wsm, S2, jg, pg, acc);
        // epilogue 1: B = sin(omega*(s*z+b1)); dB = omega*cos*s*dz
#pragma unroll
        for (int c = 0; c < 8; c++) {
            const int j = jg * 8 + c;
            const float b1 = __ldg(res_b1 + b * F + j);
            float2 z = unpack2(acc[c][0]);
            float sa, ca, sb, cb;
            __sincosf(OMEGA * fmaf(s, z.x, b1), &sa, &ca);
            __sincosf(OMEGA * fmaf(s, z.y, b1), &sb, &cb);
            const float ga = OMEGA * s * ca, gb = OMEGA * s * cb;
            B2[(0 * F + j) * 16 + po] = make_float2(sa, sb);
#pragma unroll
            for (int v = 1; v < 4; v++) {
                float2 d = unpack2(acc[c][v]);
                B2[(v * F + j) * 16 + po] = make_float2(ga * d.x, gb * d.y);
            }
        }
        __syncthreads();                       // B2 done; Wsm free
        stage(g_wt + (2 * b + 1) * F * F, Wsm, tid);
        __syncthreads();

        matmul(Wsm, B2, jg, pg, acc);
        // epilogue 2: S += sin(omega*(z+b2)); dS += omega*cos*dz
#pragma unroll
        for (int c = 0; c < 8; c++) {
            const int j = jg * 8 + c;
            const float b2 = __ldg(res_b2 + b * F + j);
            float2 z = unpack2(acc[c][0]);
            float sa, ca, sb, cb;
            __sincosf(OMEGA * (z.x + b2), &sa, &ca);
            __sincosf(OMEGA * (z.y + b2), &sb, &cb);
            const float ga = OMEGA * ca, gb = OMEGA * cb;
            {
                const int idx = (0 * F + j) * 16 + po;
                float2 o = S2[idx];
                S2[idx] = make_float2(o.x + sa, o.y + sb);
            }
#pragma unroll
            for (int v = 1; v < 4; v++) {
                const int idx = (v * F + j) * 16 + po;
                float2 d = unpack2(acc[c][v]);
                float2 o = S2[idx];
                S2[idx] = make_float2(fmaf(ga, d.x, o.x), fmaf(gb, d.y, o.y));
            }
        }
    }
    __syncthreads();

    // ---- final layer: J[p][jo][k] = final_w[jo,:] . dh_k[p]
    // Thread (jg,pg) accumulates over its i-slice [8*jg, 8*jg+8), then a
    // half-warp (width-16) shuffle reduction combines the 16 jg partials.
    ull part[4][3];
#pragma unroll
    for (int jo = 0; jo < 4; jo++)
#pragma unroll
        for (int k = 0; k < 3; k++) part[jo][k] = 0ull;

#pragma unroll
    for (int ii = 0; ii < 8; ii++) {
        const int i = jg * 8 + ii;           // (i>>3)&15 == jg -> offset po
        ull xk0 = *reinterpret_cast<const ull*>(S2 + (1 * F + i) * 16 + po);
        ull xk1 = *reinterpret_cast<const ull*>(S2 + (2 * F + i) * 16 + po);
        ull xk2 = *reinterpret_cast<const ull*>(S2 + (3 * F + i) * 16 + po);
#pragma unroll
        for (int jo = 0; jo < 4; jo++) {
            ull fw = dup2(__ldg(final_w + jo * F + i));
            part[jo][0] = ffma2(fw, xk0, part[jo][0]);
            part[jo][1] = ffma2(fw, xk1, part[jo][1]);
            part[jo][2] = ffma2(fw, xk2, part[jo][2]);
        }
    }
    float2 J[4][3];
#pragma unroll
    for (int jo = 0; jo < 4; jo++)
#pragma unroll
        for (int k = 0; k < 3; k++) J[jo][k] = unpack2(part[jo][k]);

#pragma unroll
    for (int off = 8; off; off >>= 1) {
#pragma unroll
        for (int jo = 0; jo < 4; jo++)
#pragma unroll
            for (int k = 0; k < 3; k++) {
                J[jo][k].x += __shfl_down_sync(0xffffffffu, J[jo][k].x, off, 16);
                J[jo][k].y += __shfl_down_sync(0xffffffffu, J[jo][k].y, off, 16);
            }
    }

    if (jg == 0) {
        const int p0 = blockBase + 2 * pg;
        float o0x = J[0][0].x + J[3][1].x - J[2][2].x;
        float o1x = J[0][1].x + J[1][2].x - J[3][0].x;
        float o2x = J[0][2].x + J[2][0].x - J[1][1].x;
        float o0y = J[0][0].y + J[3][1].y - J[2][2].y;
        float o1y = J[0][1].y + J[1][2].y - J[3][0].y;
        float o2y = J[0][2].y + J[2][0].y - J[1][1].y;
        out[p0 * 3 + 0] = o0x;
        out[p0 * 3 + 1] = o1x;
        out[p0 * 3 + 2] = o2x;
        out[p0 * 3 + 3] = o0y;
        out[p0 * 3 + 4] = o1y;
        out[p0 * 3 + 5] = o2y;
    }
}

extern "C" void kernel_launch(void* const* d_in, const int* in_sizes, int n_in,
                              void* d_out, int out_size) {
    const float* coords  = (const float*)d_in[0];
    const float* first_w = (const float*)d_in[1];
    const float* first_b = (const float*)d_in[2];
    const float* res_w1  = (const float*)d_in[3];
    const float* res_b1  = (const float*)d_in[4];
    const float* res_w2  = (const float*)d_in[5];
    const float* res_b2  = (const float*)d_in[6];
    const float* final_w = (const float*)d_in[7];
    // final_b (d_in[8]) drops out of the jacobian — unused.

    int n = in_sizes[0] / 3;

    transpose_weights_kernel<<<(6 * F * F + 255) / 256, 256>>>(res_w1, res_w2);

    int smem_bytes = 3 * F * F * (int)sizeof(float);   // 192KB: W + S + B
    cudaFuncSetAttribute(fsrn_kernel,
                         cudaFuncAttributeMaxDynamicSharedMemorySize, smem_bytes);
    fsrn_kernel<<<n / P, THREADS, smem_bytes>>>(
        coords, first_w, first_b, res_b1, res_b2, final_w, (float*)d_out);
}

// round 5
// speedup vs baseline: 2.4103x; 2.4103x over previous
#include <cuda_runtime.h>
#include <stdint.h>

#define F     128
#define OMEGA 30.0f
#define PIO2  1.5707963267948966f

// Weights pre-packed in B-fragment order:
// uint4 per (layer, nt, ks, lane) = {b0_hi, b1_hi, b0_lo, b1_lo},
// where b0 = bf16x2{W[n][k0], W[n][k0+1]}, b1 = {W[n][k0+8], W[n][k0+9]},
// n = 8*nt + lane/4, k0 = 16*ks + 2*(lane%4).
__device__ __align__(16) uint4 g_wfrag[6 * 4096];

// ---- smem byte layout ----
#define SM_MBAR0 0
#define SM_MBAR1 8
#define SM_CONST 64                 // 1792 floats
#define SM_J     (SM_CONST + 7168)  // 384 floats
#define SM_W0    8832               // 128-aligned
#define SM_W1    (SM_W0 + 65536)
#define SM_TOTAL (SM_W1 + 65536)    // 139904 B

// ---------------- low-level helpers ----------------
__device__ __forceinline__ uint32_t smem_u32(const void* p) {
    uint32_t a;
    asm("{ .reg .u64 t; cvta.to.shared.u64 t, %1; cvt.u32.u64 %0, t; }" : "=r"(a) : "l"(p));
    return a;
}
__device__ __forceinline__ void mbar_init(uint32_t mbar, uint32_t cnt) {
    asm volatile("mbarrier.init.shared.b64 [%0], %1;" :: "r"(mbar), "r"(cnt) : "memory");
}
__device__ __forceinline__ void mbar_expect(uint32_t mbar, uint32_t bytes) {
    asm volatile("mbarrier.arrive.expect_tx.shared.b64 _, [%0], %1;" :: "r"(mbar), "r"(bytes) : "memory");
}
__device__ __forceinline__ void mbar_wait(uint32_t mbar, int parity) {
    asm volatile(
        "{\n\t.reg .pred P;\n"
        "LW_%=:\n\t"
        "mbarrier.try_wait.parity.acquire.cta.shared::cta.b64 P, [%0], %1, 0x989680;\n\t"
        "@P bra.uni LD_%=;\n\t"
        "bra.uni LW_%=;\n"
        "LD_%=:\n\t}"
        :: "r"(mbar), "r"(parity) : "memory");
}
__device__ __forceinline__ void bulk_g2s(uint32_t dst, const void* src, uint32_t bytes, uint32_t mbar) {
    unsigned long long g = (unsigned long long)__cvta_generic_to_global(src);
    asm volatile("cp.async.bulk.shared::cluster.global.mbarrier::complete_tx::bytes [%0], [%1], %2, [%3];"
                 :: "r"(dst), "l"(g), "r"(bytes), "r"(mbar) : "memory");
}
__device__ __forceinline__ void mma16816(float4& c, const uint32_t* a, uint32_t b0, uint32_t b1) {
    asm volatile("mma.sync.aligned.m16n8k16.row.col.f32.bf16.bf16.f32 "
                 "{%0,%1,%2,%3}, {%4,%5,%6,%7}, {%8,%9}, {%0,%1,%2,%3};"
                 : "+f"(c.x), "+f"(c.y), "+f"(c.z), "+f"(c.w)
                 : "r"(a[0]), "r"(a[1]), "r"(a[2]), "r"(a[3]), "r"(b0), "r"(b1));
}
// pack (e0 -> low, e1 -> high) as bf16x2 hi, residual lo
__device__ __forceinline__ void split2(float e0, float e1, uint32_t& hi, uint32_t& lo) {
    uint32_t h;
    asm("cvt.rn.bf16x2.f32 %0, %1, %2;" : "=r"(h) : "f"(e1), "f"(e0));
    float h0 = __uint_as_float(h << 16);
    float h1 = __uint_as_float(h & 0xFFFF0000u);
    float l0 = e0 - h0, l1 = e1 - h1;
    uint32_t l;
    asm("cvt.rn.bf16x2.f32 %0, %1, %2;" : "=r"(l) : "f"(l1), "f"(l0));
    hi = h; lo = l;
}
__device__ __forceinline__ float2 upk2(uint32_t hi, uint32_t lo) {
    float2 r;
    r.x = __uint_as_float(hi << 16) + __uint_as_float(lo << 16);
    r.y = __uint_as_float(hi & 0xFFFF0000u) + __uint_as_float(lo & 0xFFFF0000u);
    return r;
}

// ---------------- prep: pack weights into fragment order ----------------
__global__ void prep_kernel(const float* __restrict__ rw1, const float* __restrict__ rw2) {
    int t = blockIdx.x * blockDim.x + threadIdx.x;
    if (t >= 6 * 4096) return;
    int layer = t >> 12;
    int e = t & 4095;
    int lane = e & 31, ks = (e >> 5) & 7, nt = e >> 8;
    int n = 8 * nt + (lane >> 2);
    int k0 = 16 * ks + 2 * (lane & 3);
    int b = layer >> 1;
    const float* W = ((layer & 1) ? rw2 : rw1) + b * F * F;
    float w00 = W[n * F + k0],     w01 = W[n * F + k0 + 1];
    float w10 = W[n * F + k0 + 8], w11 = W[n * F + k0 + 9];
    uint32_t h0, l0, h1, l1;
    split2(w00, w01, h0, l0);
    split2(w10, w11, h1, l1);
    g_wfrag[layer * 4096 + e] = make_uint4(h0, h1, l0, l1);
}

// ---------------- MMA over one layer: 3 split passes ----------------
__device__ __forceinline__ void do_mma(const uint4* __restrict__ w4, int lane,
                                       const uint32_t* Ah, const uint32_t* Al, float4* acc) {
#pragma unroll
    for (int ks = 0; ks < 8; ks++) {
#pragma unroll
        for (int nt = 0; nt < 16; nt++) {
            uint4 bb = w4[(nt * 8 + ks) * 32 + lane];
            mma16816(acc[nt], Ah + 4 * ks, bb.x, bb.y);   // hi * Whi
            mma16816(acc[nt], Al + 4 * ks, bb.x, bb.y);   // lo * Whi
            mma16816(acc[nt], Ah + 4 * ks, bb.z, bb.w);   // hi * Wlo
        }
    }
}

// ---------------- main kernel ----------------
__global__ void __launch_bounds__(256, 1)
fsrn_mma(const float* __restrict__ coords,
         const float* __restrict__ first_w, const float* __restrict__ first_b,
         const float* __restrict__ res_b1,  const float* __restrict__ res_b2,
         const float* __restrict__ final_w, float* __restrict__ out) {
    extern __shared__ unsigned char smem[];
    const uint32_t sb = smem_u32(smem);
    const int tid = threadIdx.x, w = tid >> 5, lane = tid & 31;
    const int gr = lane >> 2, tig = lane & 3;
    const int lz = lane & ~12;            // lane holding the primal-row acc
    const int r0 = w * 16 + gr;           // rows r0 and r0+8
    const int ch = r0 & 3;
    const int pt0 = r0 >> 2, pt1 = (r0 + 8) >> 2;
    const bool primal = (ch == 0);
    const float ph = primal ? 0.0f : PIO2;

    const uint32_t mb0 = sb + SM_MBAR0, mb1 = sb + SM_MBAR1;
    if (tid == 0) { mbar_init(mb0, 1); mbar_init(mb1, 1); }
    __syncthreads();
    if (tid == 0) {
        mbar_expect(mb0, 65536); bulk_g2s(sb + SM_W0, g_wfrag,        65536, mb0);
        mbar_expect(mb1, 65536); bulk_g2s(sb + SM_W1, g_wfrag + 4096, 65536, mb1);
    }

    // ---- stage constants
    float* cs = (float*)(smem + SM_CONST);
    for (int i = tid; i < 1792; i += 256) {
        float v;
        if (i < 128)       v = first_b[i];
        else if (i < 512)  { int idx = i - 128; v = first_w[(idx & 127) * 3 + (idx >> 7)]; }
        else if (i < 896)  v = res_b1[i - 512];
        else if (i < 1280) v = res_b2[i - 896];
        else               v = final_w[i - 1280];
        cs[i] = v;
    }
    __syncthreads();
    const float* fb_s  = cs;
    const float* fwT   = cs + 128;     // [k*128 + n]
    const float* rb1_s = cs + 512;
    const float* rb2_s = cs + 896;
    const float* fwf   = cs + 1280;    // [jo*128 + n]

    uint32_t Sh[32], Sl[32], Ah[32], Al[32];

    // ---- first layer (registers only)
    {
        int gp0 = blockIdx.x * 32 + pt0, gp1 = blockIdx.x * 32 + pt1;
        float c0x = coords[gp0 * 3], c0y = coords[gp0 * 3 + 1], c0z = coords[gp0 * 3 + 2];
        float c1x = coords[gp1 * 3], c1y = coords[gp1 * 3 + 1], c1z = coords[gp1 * 3 + 2];
        const float* fsel = fwT + (primal ? 0 : (ch - 1)) * 128;
#pragma unroll
        for (int nt = 0; nt < 16; nt++) {
            int n0 = 8 * nt + 2 * tig;
            float e0[2], e1[2];
#pragma unroll
            for (int q = 0; q < 2; q++) {
                int n = n0 + q;
                float f0 = fwT[n], f1 = fwT[128 + n], f2 = fwT[256 + n], fb = fb_s[n];
                float zb0 = fmaf(f0, c0x, fmaf(f1, c0y, fmaf(f2, c0z, fb)));
                float zb1 = fmaf(f0, c1x, fmaf(f1, c1y, fmaf(f2, c1z, fb)));
                float fac = primal ? 1.0f : OMEGA * fsel[n];
                e0[q] = __sinf(fmaf(OMEGA, zb0, ph)) * fac;
                e1[q] = __sinf(fmaf(OMEGA, zb1, ph)) * fac;
            }
            split2(e0[0], e0[1], Sh[2 * nt],     Sl[2 * nt]);
            split2(e1[0], e1[1], Sh[2 * nt + 1], Sl[2 * nt + 1]);
        }
    }

    const uint4* w40 = (const uint4*)(smem + SM_W0);
    const uint4* w41 = (const uint4*)(smem + SM_W1);
    float4 acc[16];

    // ---- 3 residual blocks (2 layers each)
    for (int b = 0; b < 3; b++) {
        const float s = (b == 0) ? 1.0f : 0.5f;
        const float OmS = OMEGA * s;

        // ===== layer 2b (w1): A = S
        mbar_wait(mb0, b & 1);
#pragma unroll
        for (int i = 0; i < 16; i++) acc[i] = make_float4(0.f, 0.f, 0.f, 0.f);
        do_mma(w40, lane, Sh, Sl, acc);
        __syncthreads();
        if (tid == 0 && b < 2) {
            mbar_expect(mb0, 65536);
            bulk_g2s(sb + SM_W0, g_wfrag + (2 * b + 2) * 4096, 65536, mb0);
        }
        {   // epilogue: B1 = sin(Ω(s z + b1) [+π/2]) [* Ωs dz]  -> Ah/Al
            const float* bias = rb1_s + b * 128;
#pragma unroll
            for (int nt = 0; nt < 16; nt++) {
                int n0 = 8 * nt + 2 * tig;
                float ob0 = fmaf(OMEGA, bias[n0], ph);
                float ob1 = fmaf(OMEGA, bias[n0 + 1], ph);
                float4 a = acc[nt];
                float z0 = __shfl_sync(0xffffffffu, a.x, lz);
                float z1 = __shfl_sync(0xffffffffu, a.y, lz);
                float z2 = __shfl_sync(0xffffffffu, a.z, lz);
                float z3 = __shfl_sync(0xffffffffu, a.w, lz);
                float v0 = __sinf(fmaf(OmS, z0, ob0));
                float v1 = __sinf(fmaf(OmS, z1, ob1));
                float v2 = __sinf(fmaf(OmS, z2, ob0));
                float v3 = __sinf(fmaf(OmS, z3, ob1));
                float e0 = primal ? v0 : OmS * v0 * a.x;
                float e1 = primal ? v1 : OmS * v1 * a.y;
                float e2 = primal ? v2 : OmS * v2 * a.z;
                float e3 = primal ? v3 : OmS * v3 * a.w;
                split2(e0, e1, Ah[2 * nt],     Al[2 * nt]);
                split2(e2, e3, Ah[2 * nt + 1], Al[2 * nt + 1]);
            }
        }

        // ===== layer 2b+1 (w2): A = B1
        mbar_wait(mb1, b & 1);
#pragma unroll
        for (int i = 0; i < 16; i++) acc[i] = make_float4(0.f, 0.f, 0.f, 0.f);
        do_mma(w41, lane, Ah, Al, acc);
        __syncthreads();
        if (tid == 0 && b < 2) {
            mbar_expect(mb1, 65536);
            bulk_g2s(sb + SM_W1, g_wfrag + (2 * b + 3) * 4096, 65536, mb1);
        }
        {   // epilogue: S += sin(Ω(z + b2) [+π/2]) [* Ω dz]
            const float* bias = rb2_s + b * 128;
#pragma unroll
            for (int nt = 0; nt < 16; nt++) {
                int n0 = 8 * nt + 2 * tig;
                float ob0 = fmaf(OMEGA, bias[n0], ph);
                float ob1 = fmaf(OMEGA, bias[n0 + 1], ph);
                float4 a = acc[nt];
                float z0 = __shfl_sync(0xffffffffu, a.x, lz);
                float z1 = __shfl_sync(0xffffffffu, a.y, lz);
                float z2 = __shfl_sync(0xffffffffu, a.z, lz);
                float z3 = __shfl_sync(0xffffffffu, a.w, lz);
                float v0 = __sinf(fmaf(OMEGA, z0, ob0));
                float v1 = __sinf(fmaf(OMEGA, z1, ob1));
                float v2 = __sinf(fmaf(OMEGA, z2, ob0));
                float v3 = __sinf(fmaf(OMEGA, z3, ob1));
                float e0 = primal ? v0 : OMEGA * v0 * a.x;
                float e1 = primal ? v1 : OMEGA * v1 * a.y;
                float e2 = primal ? v2 : OMEGA * v2 * a.z;
                float e3 = primal ? v3 : OMEGA * v3 * a.w;
                float2 p0 = upk2(Sh[2 * nt], Sl[2 * nt]);
                float2 p1 = upk2(Sh[2 * nt + 1], Sl[2 * nt + 1]);
                split2(p0.x + e0, p0.y + e1, Sh[2 * nt],     Sl[2 * nt]);
                split2(p1.x + e2, p1.y + e3, Sh[2 * nt + 1], Sl[2 * nt + 1]);
            }
        }
    }

    // ---- final layer: J[p][jo][k] = final_w[jo] . dh_k[p] (tangent rows only)
    float J0[4] = {0.f, 0.f, 0.f, 0.f};
    float J1[4] = {0.f, 0.f, 0.f, 0.f};
#pragma unroll
    for (int nt = 0; nt < 16; nt++) {
        int n0 = 8 * nt + 2 * tig;
        float2 p0 = upk2(Sh[2 * nt],     Sl[2 * nt]);
        float2 p1 = upk2(Sh[2 * nt + 1], Sl[2 * nt + 1]);
#pragma unroll
        for (int jo = 0; jo < 4; jo++) {
            float f0 = fwf[jo * 128 + n0], f1 = fwf[jo * 128 + n0 + 1];
            J0[jo] = fmaf(f0, p0.x, fmaf(f1, p0.y, J0[jo]));
            J1[jo] = fmaf(f0, p1.x, fmaf(f1, p1.y, J1[jo]));
        }
    }
#pragma unroll
    for (int off = 1; off <= 2; off <<= 1) {
#pragma unroll
        for (int jo = 0; jo < 4; jo++) {
            J0[jo] += __shfl_xor_sync(0xffffffffu, J0[jo], off);
            J1[jo] += __shfl_xor_sync(0xffffffffu, J1[jo], off);
        }
    }
    float* Jsh = (float*)(smem + SM_J);
    if (tig == 0 && ch != 0) {
#pragma unroll
        for (int jo = 0; jo < 4; jo++) {
            Jsh[pt0 * 12 + jo * 3 + (ch - 1)] = J0[jo];
            Jsh[pt1 * 12 + jo * 3 + (ch - 1)] = J1[jo];
        }
    }
    __syncthreads();

    if (tid < 32) {
        const float* Jp = Jsh + tid * 12;          // [jo*3 + k]
        int gp = blockIdx.x * 32 + tid;
        out[gp * 3 + 0] = Jp[0] + Jp[10] - Jp[8];  // J00 + J31 - J22
        out[gp * 3 + 1] = Jp[1] + Jp[5]  - Jp[9];  // J01 + J12 - J30
        out[gp * 3 + 2] = Jp[2] + Jp[6]  - Jp[4];  // J02 + J20 - J11
    }
}

extern "C" void kernel_launch(void* const* d_in, const int* in_sizes, int n_in,
                              void* d_out, int out_size) {
    const float* coords  = (const float*)d_in[0];
    const float* first_w = (const float*)d_in[1];
    const float* first_b = (const float*)d_in[2];
    const float* res_w1  = (const float*)d_in[3];
    const float* res_b1  = (const float*)d_in[4];
    const float* res_w2  = (const float*)d_in[5];
    const float* res_b2  = (const float*)d_in[6];
    const float* final_w = (const float*)d_in[7];
    // final_b (d_in[8]) drops out of the jacobian — unused.

    int n = in_sizes[0] / 3;

    prep_kernel<<<(6 * 4096 + 255) / 256, 256>>>(res_w1, res_w2);

    cudaFuncSetAttribute(fsrn_mma, cudaFuncAttributeMaxDynamicSharedMemorySize, SM_TOTAL);
    fsrn_mma<<<n / 32, 256, SM_TOTAL>>>(coords, first_w, first_b,
                                        res_b1, res_b2, final_w, (float*)d_out);
}

// round 6
// speedup vs baseline: 2.4784x; 1.0283x over previous
#include <cuda_runtime.h>
#include <stdint.h>

#define F     128
#define OMEGA 30.0f
#define PIO2  1.5707963267948966f

// Weights pre-packed in B-fragment order:
// uint4 per (layer, nt, ks, lane) = {b0_hi, b1_hi, b0_lo, b1_lo},
// where b0 = bf16x2{W[n][k0], W[n][k0+1]}, b1 = {W[n][k0+8], W[n][k0+9]},
// n = 8*nt + lane/4, k0 = 16*ks + 2*(lane%4).
__device__ __align__(16) uint4 g_wfrag[6 * 4096];

// ---- smem byte layout ----
#define SM_MBAR_R0 0
#define SM_MBAR_R1 8
#define SM_MBAR_F0 16
#define SM_MBAR_F1 24
#define SM_CONST 64                 // 1792 floats
#define SM_J     (SM_CONST + 7168)  // 384 floats
#define SM_W0    8832               // 128-aligned
#define SM_W1    (SM_W0 + 65536)
#define SM_TOTAL (SM_W1 + 65536)    // 139904 B

// ---------------- low-level helpers ----------------
__device__ __forceinline__ uint32_t smem_u32(const void* p) {
    uint32_t a;
    asm("{ .reg .u64 t; cvta.to.shared.u64 t, %1; cvt.u32.u64 %0, t; }" : "=r"(a) : "l"(p));
    return a;
}
__device__ __forceinline__ void mbar_init(uint32_t mbar, uint32_t cnt) {
    asm volatile("mbarrier.init.shared.b64 [%0], %1;" :: "r"(mbar), "r"(cnt) : "memory");
}
__device__ __forceinline__ void mbar_expect(uint32_t mbar, uint32_t bytes) {
    asm volatile("mbarrier.arrive.expect_tx.shared.b64 _, [%0], %1;" :: "r"(mbar), "r"(bytes) : "memory");
}
__device__ __forceinline__ void mbar_arrive(uint32_t mbar) {
    asm volatile("mbarrier.arrive.shared.b64 _, [%0];" :: "r"(mbar) : "memory");
}
__device__ __forceinline__ void mbar_wait(uint32_t mbar, int parity) {
    asm volatile(
        "{\n\t.reg .pred P;\n"
        "LW_%=:\n\t"
        "mbarrier.try_wait.parity.acquire.cta.shared::cta.b64 P, [%0], %1, 0x989680;\n\t"
        "@P bra.uni LD_%=;\n\t"
        "bra.uni LW_%=;\n"
        "LD_%=:\n\t}"
        :: "r"(mbar), "r"(parity) : "memory");
}
__device__ __forceinline__ void bulk_g2s(uint32_t dst, const void* src, uint32_t bytes, uint32_t mbar) {
    unsigned long long g = (unsigned long long)__cvta_generic_to_global(src);
    asm volatile("cp.async.bulk.shared::cluster.global.mbarrier::complete_tx::bytes [%0], [%1], %2, [%3];"
                 :: "r"(dst), "l"(g), "r"(bytes), "r"(mbar) : "memory");
}
__device__ __forceinline__ void mma16816(float4& c, const uint32_t* a, uint32_t b0, uint32_t b1) {
    asm volatile("mma.sync.aligned.m16n8k16.row.col.f32.bf16.bf16.f32 "
                 "{%0,%1,%2,%3}, {%4,%5,%6,%7}, {%8,%9}, {%0,%1,%2,%3};"
                 : "+f"(c.x), "+f"(c.y), "+f"(c.z), "+f"(c.w)
                 : "r"(a[0]), "r"(a[1]), "r"(a[2]), "r"(a[3]), "r"(b0), "r"(b1));
}
// pack (e0 -> low, e1 -> high) as bf16x2 hi, residual lo
__device__ __forceinline__ void split2(float e0, float e1, uint32_t& hi, uint32_t& lo) {
    uint32_t h;
    asm("cvt.rn.bf16x2.f32 %0, %1, %2;" : "=r"(h) : "f"(e1), "f"(e0));
    float h0 = __uint_as_float(h << 16);
    float h1 = __uint_as_float(h & 0xFFFF0000u);
    float l0 = e0 - h0, l1 = e1 - h1;
    uint32_t l;
    asm("cvt.rn.bf16x2.f32 %0, %1, %2;" : "=r"(l) : "f"(l1), "f"(l0));
    hi = h; lo = l;
}
__device__ __forceinline__ float2 upk2(uint32_t hi, uint32_t lo) {
    float2 r;
    r.x = __uint_as_float(hi << 16) + __uint_as_float(lo << 16);
    r.y = __uint_as_float(hi & 0xFFFF0000u) + __uint_as_float(lo & 0xFFFF0000u);
    return r;
}

// ---------------- prep: pack weights into fragment order ----------------
__global__ void prep_kernel(const float* __restrict__ rw1, const float* __restrict__ rw2) {
    int t = blockIdx.x * blockDim.x + threadIdx.x;
    if (t >= 6 * 4096) return;
    int layer = t >> 12;
    int e = t & 4095;
    int lane = e & 31, ks = (e >> 5) & 7, nt = e >> 8;
    int n = 8 * nt + (lane >> 2);
    int k0 = 16 * ks + 2 * (lane & 3);
    int b = layer >> 1;
    const float* W = ((layer & 1) ? rw2 : rw1) + b * F * F;
    float w00 = W[n * F + k0],     w01 = W[n * F + k0 + 1];
    float w10 = W[n * F + k0 + 8], w11 = W[n * F + k0 + 9];
    uint32_t h0, l0, h1, l1;
    split2(w00, w01, h0, l0);
    split2(w10, w11, h1, l1);
    g_wfrag[layer * 4096 + e] = make_uint4(h0, h1, l0, l1);
}

// ---------------- MMA over one layer: 3 split passes ----------------
__device__ __forceinline__ void do_mma(const uint4* __restrict__ w4, int lane,
                                       const uint32_t* Ah, const uint32_t* Al, float4* acc) {
#pragma unroll
    for (int ks = 0; ks < 8; ks++) {
#pragma unroll
        for (int nt = 0; nt < 16; nt++) {
            uint4 bb = w4[(nt * 8 + ks) * 32 + lane];
            mma16816(acc[nt], Ah + 4 * ks, bb.x, bb.y);   // hi * Whi
            mma16816(acc[nt], Al + 4 * ks, bb.x, bb.y);   // lo * Whi
            mma16816(acc[nt], Ah + 4 * ks, bb.z, bb.w);   // hi * Wlo
        }
    }
}

// ---------------- main kernel ----------------
__global__ void __launch_bounds__(256, 1)
fsrn_mma(const float* __restrict__ coords,
         const float* __restrict__ first_w, const float* __restrict__ first_b,
         const float* __restrict__ res_b1,  const float* __restrict__ res_b2,
         const float* __restrict__ final_w, float* __restrict__ out) {
    extern __shared__ unsigned char smem[];
    const uint32_t sb = smem_u32(smem);
    const int tid = threadIdx.x, w = tid >> 5, lane = tid & 31;
    const int gr = lane >> 2, tig = lane & 3;
    const int lz = lane & ~12;            // lane holding the primal-row acc
    const int r0 = w * 16 + gr;           // rows r0 and r0+8
    const int ch = r0 & 3;
    const int pt0 = r0 >> 2, pt1 = (r0 + 8) >> 2;
    const bool primal = (ch == 0);
    const float ph = primal ? 0.0f : PIO2;

    const uint32_t mbr0 = sb + SM_MBAR_R0, mbr1 = sb + SM_MBAR_R1;
    const uint32_t mbf0 = sb + SM_MBAR_F0, mbf1 = sb + SM_MBAR_F1;
    if (tid == 0) {
        mbar_init(mbr0, 1); mbar_init(mbr1, 1);
        mbar_init(mbf0, 8); mbar_init(mbf1, 8);
    }
    __syncthreads();
    if (tid == 0) {
        mbar_expect(mbr0, 65536); bulk_g2s(sb + SM_W0, g_wfrag,        65536, mbr0);
        mbar_expect(mbr1, 65536); bulk_g2s(sb + SM_W1, g_wfrag + 4096, 65536, mbr1);
    }

    // ---- stage constants
    float* cs = (float*)(smem + SM_CONST);
    for (int i = tid; i < 1792; i += 256) {
        float v;
        if (i < 128)       v = first_b[i];
        else if (i < 512)  { int idx = i - 128; v = first_w[(idx & 127) * 3 + (idx >> 7)]; }
        else if (i < 896)  v = res_b1[i - 512];
        else if (i < 1280) v = res_b2[i - 896];
        else               v = final_w[i - 1280];
        cs[i] = v;
    }
    __syncthreads();
    const float* fb_s  = cs;
    const float* fwT   = cs + 128;     // [k*128 + n]
    const float* rb1_s = cs + 512;
    const float* rb2_s = cs + 896;
    const float* fwf   = cs + 1280;    // [jo*128 + n]

    uint32_t Sh[32], Sl[32], Ah[32], Al[32];

    // ---- first layer (registers only)
    {
        int gp0 = blockIdx.x * 32 + pt0, gp1 = blockIdx.x * 32 + pt1;
        float c0x = coords[gp0 * 3], c0y = coords[gp0 * 3 + 1], c0z = coords[gp0 * 3 + 2];
        float c1x = coords[gp1 * 3], c1y = coords[gp1 * 3 + 1], c1z = coords[gp1 * 3 + 2];
        const float* fsel = fwT + (primal ? 0 : (ch - 1)) * 128;
#pragma unroll
        for (int nt = 0; nt < 16; nt++) {
            int n0 = 8 * nt + 2 * tig;
            float e0[2], e1[2];
#pragma unroll
            for (int q = 0; q < 2; q++) {
                int n = n0 + q;
                float f0 = fwT[n], f1 = fwT[128 + n], f2 = fwT[256 + n], fb = fb_s[n];
                float zb0 = fmaf(f0, c0x, fmaf(f1, c0y, fmaf(f2, c0z, fb)));
                float zb1 = fmaf(f0, c1x, fmaf(f1, c1y, fmaf(f2, c1z, fb)));
                float fac = primal ? 1.0f : OMEGA * fsel[n];
                e0[q] = __sinf(fmaf(OMEGA, zb0, ph)) * fac;
                e1[q] = __sinf(fmaf(OMEGA, zb1, ph)) * fac;
            }
            split2(e0[0], e0[1], Sh[2 * nt],     Sl[2 * nt]);
            split2(e1[0], e1[1], Sh[2 * nt + 1], Sl[2 * nt + 1]);
        }
    }

    const uint4* w40 = (const uint4*)(smem + SM_W0);
    const uint4* w41 = (const uint4*)(smem + SM_W1);
    float4 acc[16];

    // ---- 3 residual blocks (2 layers each), no CTA barriers in the loop:
    // ready mbarriers (tx) gate weight consumption; free mbarriers (8 warp
    // arrivals, posted right after each warp's MMA reads) gate re-prefetch.
    for (int b = 0; b < 3; b++) {
        const float s = (b == 0) ? 1.0f : 0.5f;
        const float OmS = OMEGA * s;

        // ===== layer 2b (w1): A = S, weights in W0
        mbar_wait(mbr0, b & 1);
#pragma unroll
        for (int i = 0; i < 16; i++) acc[i] = make_float4(0.f, 0.f, 0.f, 0.f);
        do_mma(w40, lane, Sh, Sl, acc);
        if (lane == 0) mbar_arrive(mbf0);
        {   // epilogue: B1 = sin(Ω(s z + b1) [+π/2]) [* Ωs dz]  -> Ah/Al
            const float* bias = rb1_s + b * 128;
#pragma unroll
            for (int nt = 0; nt < 16; nt++) {
                int n0 = 8 * nt + 2 * tig;
                float ob0 = fmaf(OMEGA, bias[n0], ph);
                float ob1 = fmaf(OMEGA, bias[n0 + 1], ph);
                float4 a = acc[nt];
                float z0 = __shfl_sync(0xffffffffu, a.x, lz);
                float z1 = __shfl_sync(0xffffffffu, a.y, lz);
                float z2 = __shfl_sync(0xffffffffu, a.z, lz);
                float z3 = __shfl_sync(0xffffffffu, a.w, lz);
                float v0 = __sinf(fmaf(OmS, z0, ob0));
                float v1 = __sinf(fmaf(OmS, z1, ob1));
                float v2 = __sinf(fmaf(OmS, z2, ob0));
                float v3 = __sinf(fmaf(OmS, z3, ob1));
                float e0 = primal ? v0 : OmS * v0 * a.x;
                float e1 = primal ? v1 : OmS * v1 * a.y;
                float e2 = primal ? v2 : OmS * v2 * a.z;
                float e3 = primal ? v3 : OmS * v3 * a.w;
                split2(e0, e1, Ah[2 * nt],     Al[2 * nt]);
                split2(e2, e3, Ah[2 * nt + 1], Al[2 * nt + 1]);
            }
        }
        if (tid == 0 && b < 2) {       // refill W0 with layer 2b+2
            mbar_wait(mbf0, b);
            mbar_expect(mbr0, 65536);
            bulk_g2s(sb + SM_W0, g_wfrag + (2 * b + 2) * 4096, 65536, mbr0);
        }

        // ===== layer 2b+1 (w2): A = B1, weights in W1
        mbar_wait(mbr1, b & 1);
#pragma unroll
        for (int i = 0; i < 16; i++) acc[i] = make_float4(0.f, 0.f, 0.f, 0.f);
        do_mma(w41, lane, Ah, Al, acc);
        if (lane == 0) mbar_arrive(mbf1);
        {   // epilogue: S += sin(Ω(z + b2) [+π/2]) [* Ω dz]
            const float* bias = rb2_s + b * 128;
#pragma unroll
            for (int nt = 0; nt < 16; nt++) {
                int n0 = 8 * nt + 2 * tig;
                float ob0 = fmaf(OMEGA, bias[n0], ph);
                float ob1 = fmaf(OMEGA, bias[n0 + 1], ph);
                float4 a = acc[nt];
                float z0 = __shfl_sync(0xffffffffu, a.x, lz);
                float z1 = __shfl_sync(0xffffffffu, a.y, lz);
                float z2 = __shfl_sync(0xffffffffu, a.z, lz);
                float z3 = __shfl_sync(0xffffffffu, a.w, lz);
                float v0 = __sinf(fmaf(OMEGA, z0, ob0));
                float v1 = __sinf(fmaf(OMEGA, z1, ob1));
                float v2 = __sinf(fmaf(OMEGA, z2, ob0));
                float v3 = __sinf(fmaf(OMEGA, z3, ob1));
                float e0 = primal ? v0 : OMEGA * v0 * a.x;
                float e1 = primal ? v1 : OMEGA * v1 * a.y;
                float e2 = primal ? v2 : OMEGA * v2 * a.z;
                float e3 = primal ? v3 : OMEGA * v3 * a.w;
                float2 p0 = upk2(Sh[2 * nt], Sl[2 * nt]);
                float2 p1 = upk2(Sh[2 * nt + 1], Sl[2 * nt + 1]);
                split2(p0.x + e0, p0.y + e1, Sh[2 * nt],     Sl[2 * nt]);
                split2(p1.x + e2, p1.y + e3, Sh[2 * nt + 1], Sl[2 * nt + 1]);
            }
        }
        if (tid == 0 && b < 2) {       // refill W1 with layer 2b+3
            mbar_wait(mbf1, b);
            mbar_expect(mbr1, 65536);
            bulk_g2s(sb + SM_W1, g_wfrag + (2 * b + 3) * 4096, 65536, mbr1);
        }
    }

    // ---- final layer: J[p][jo][k] = final_w[jo] . dh_k[p] (tangent rows only)
    float J0[4] = {0.f, 0.f, 0.f, 0.f};
    float J1[4] = {0.f, 0.f, 0.f, 0.f};
#pragma unroll
    for (int nt = 0; nt < 16; nt++) {
        int n0 = 8 * nt + 2 * tig;
        float2 p0 = upk2(Sh[2 * nt],     Sl[2 * nt]);
        float2 p1 = upk2(Sh[2 * nt + 1], Sl[2 * nt + 1]);
#pragma unroll
        for (int jo = 0; jo < 4; jo++) {
            float f0 = fwf[jo * 128 + n0], f1 = fwf[jo * 128 + n0 + 1];
            J0[jo] = fmaf(f0, p0.x, fmaf(f1, p0.y, J0[jo]));
            J1[jo] = fmaf(f0, p1.x, fmaf(f1, p1.y, J1[jo]));
        }
    }
#pragma unroll
    for (int off = 1; off <= 2; off <<= 1) {
#pragma unroll
        for (int jo = 0; jo < 4; jo++) {
            J0[jo] += __shfl_xor_sync(0xffffffffu, J0[jo], off);
            J1[jo] += __shfl_xor_sync(0xffffffffu, J1[jo], off);
        }
    }
    float* Jsh = (float*)(smem + SM_J);
    if (tig == 0 && ch != 0) {
#pragma unroll
        for (int jo = 0; jo < 4; jo++) {
            Jsh[pt0 * 12 + jo * 3 + (ch - 1)] = J0[jo];
            Jsh[pt1 * 12 + jo * 3 + (ch - 1)] = J1[jo];
        }
    }
    __syncthreads();

    if (tid < 32) {
        const float* Jp = Jsh + tid * 12;          // [jo*3 + k]
        int gp = blockIdx.x * 32 + tid;
        out[gp * 3 + 0] = Jp[0] + Jp[10] - Jp[8];  // J00 + J31 - J22
        out[gp * 3 + 1] = Jp[1] + Jp[5]  - Jp[9];  // J01 + J12 - J30
        out[gp * 3 + 2] = Jp[2] + Jp[6]  - Jp[4];  // J02 + J20 - J11
    }
}

extern "C" void kernel_launch(void* const* d_in, const int* in_sizes, int n_in,
                              void* d_out, int out_size) {
    const float* coords  = (const float*)d_in[0];
    const float* first_w = (const float*)d_in[1];
    const float* first_b = (const float*)d_in[2];
    const float* res_w1  = (const float*)d_in[3];
    const float* res_b1  = (const float*)d_in[4];
    const float* res_w2  = (const float*)d_in[5];
    const float* res_b2  = (const float*)d_in[6];
    const float* final_w = (const float*)d_in[7];
    // final_b (d_in[8]) drops out of the jacobian — unused.

    int n = in_sizes[0] / 3;

    prep_kernel<<<(6 * 4096 + 255) / 256, 256>>>(res_w1, res_w2);

    cudaFuncSetAttribute(fsrn_mma, cudaFuncAttributeMaxDynamicSharedMemorySize, SM_TOTAL);
    fsrn_mma<<<n / 32, 256, SM_TOTAL>>>(coords, first_w, first_b,
                                        res_b1, res_b2, final_w, (float*)d_out);
}

// round 7
// speedup vs baseline: 2.5402x; 1.0250x over previous
#include <cuda_runtime.h>
#include <stdint.h>

#define F     128
#define OMEGA 30.0f
#define PIO2  1.5707963267948966f

// Weights pre-packed in B-fragment order:
// uint4 per (layer, nt, ks, lane) = {b0_hi, b1_hi, b0_lo, b1_lo},
// where b0 = bf16x2{W[n][k0], W[n][k0+1]}, b1 = {W[n][k0+8], W[n][k0+9]},
// n = 8*nt + lane/4, k0 = 16*ks + 2*(lane%4).
__device__ __align__(16) uint4 g_wfrag[6 * 4096];

// ---- smem byte layout ----
#define SM_MBAR_R0 0
#define SM_MBAR_R1 8
#define SM_MBAR_F0 16
#define SM_MBAR_F1 24
#define SM_CONST 64                 // 1792 floats
#define SM_J     (SM_CONST + 7168)  // 384 floats
#define SM_W0    8832               // 128-aligned
#define SM_W1    (SM_W0 + 65536)
#define SM_TOTAL (SM_W1 + 65536)    // 139904 B

// ---------------- low-level helpers ----------------
__device__ __forceinline__ uint32_t smem_u32(const void* p) {
    uint32_t a;
    asm("{ .reg .u64 t; cvta.to.shared.u64 t, %1; cvt.u32.u64 %0, t; }" : "=r"(a) : "l"(p));
    return a;
}
__device__ __forceinline__ void mbar_init(uint32_t mbar, uint32_t cnt) {
    asm volatile("mbarrier.init.shared.b64 [%0], %1;" :: "r"(mbar), "r"(cnt) : "memory");
}
__device__ __forceinline__ void mbar_expect(uint32_t mbar, uint32_t bytes) {
    asm volatile("mbarrier.arrive.expect_tx.shared.b64 _, [%0], %1;" :: "r"(mbar), "r"(bytes) : "memory");
}
__device__ __forceinline__ void mbar_arrive(uint32_t mbar) {
    asm volatile("mbarrier.arrive.shared.b64 _, [%0];" :: "r"(mbar) : "memory");
}
__device__ __forceinline__ void mbar_wait(uint32_t mbar, int parity) {
    asm volatile(
        "{\n\t.reg .pred P;\n"
        "LW_%=:\n\t"
        "mbarrier.try_wait.parity.acquire.cta.shared::cta.b64 P, [%0], %1, 0x989680;\n\t"
        "@P bra.uni LD_%=;\n\t"
        "bra.uni LW_%=;\n"
        "LD_%=:\n\t}"
        :: "r"(mbar), "r"(parity) : "memory");
}
__device__ __forceinline__ void bulk_g2s(uint32_t dst, const void* src, uint32_t bytes, uint32_t mbar) {
    unsigned long long g = (unsigned long long)__cvta_generic_to_global(src);
    asm volatile("cp.async.bulk.shared::cluster.global.mbarrier::complete_tx::bytes [%0], [%1], %2, [%3];"
                 :: "r"(dst), "l"(g), "r"(bytes), "r"(mbar) : "memory");
}
__device__ __forceinline__ void mma16816(float4& c, const uint32_t* a, uint32_t b0, uint32_t b1) {
    asm volatile("mma.sync.aligned.m16n8k16.row.col.f32.bf16.bf16.f32 "
                 "{%0,%1,%2,%3}, {%4,%5,%6,%7}, {%8,%9}, {%0,%1,%2,%3};"
                 : "+f"(c.x), "+f"(c.y), "+f"(c.z), "+f"(c.w)
                 : "r"(a[0]), "r"(a[1]), "r"(a[2]), "r"(a[3]), "r"(b0), "r"(b1));
}
// pack (e0 -> low, e1 -> high) as bf16x2 hi, residual lo
__device__ __forceinline__ void split2(float e0, float e1, uint32_t& hi, uint32_t& lo) {
    uint32_t h;
    asm("cvt.rn.bf16x2.f32 %0, %1, %2;" : "=r"(h) : "f"(e1), "f"(e0));
    float h0 = __uint_as_float(h << 16);
    float h1 = __uint_as_float(h & 0xFFFF0000u);
    float l0 = e0 - h0, l1 = e1 - h1;
    uint32_t l;
    asm("cvt.rn.bf16x2.f32 %0, %1, %2;" : "=r"(l) : "f"(l1), "f"(l0));
    hi = h; lo = l;
}
__device__ __forceinline__ float2 upk2(uint32_t hi, uint32_t lo) {
    float2 r;
    r.x = __uint_as_float(hi << 16) + __uint_as_float(lo << 16);
    r.y = __uint_as_float(hi & 0xFFFF0000u) + __uint_as_float(lo & 0xFFFF0000u);
    return r;
}

// ---------------- prep: pack weights into fragment order ----------------
__global__ void prep_kernel(const float* __restrict__ rw1, const float* __restrict__ rw2) {
    int t = blockIdx.x * blockDim.x + threadIdx.x;
    if (t >= 6 * 4096) return;
    int layer = t >> 12;
    int e = t & 4095;
    int lane = e & 31, ks = (e >> 5) & 7, nt = e >> 8;
    int n = 8 * nt + (lane >> 2);
    int k0 = 16 * ks + 2 * (lane & 3);
    int b = layer >> 1;
    const float* W = ((layer & 1) ? rw2 : rw1) + b * F * F;
    float w00 = W[n * F + k0],     w01 = W[n * F + k0 + 1];
    float w10 = W[n * F + k0 + 8], w11 = W[n * F + k0 + 9];
    uint32_t h0, l0, h1, l1;
    split2(w00, w01, h0, l0);
    split2(w10, w11, h1, l1);
    g_wfrag[layer * 4096 + e] = make_uint4(h0, h1, l0, l1);
}

// ---------------- fused layer: per n-tile MMA + epilogue ----------------
// For each of 16 n-tiles: 24 MMAs complete acc, then that tile's activation
// epilogue runs immediately -> its MUFU/ALU work overlaps the next tile's
// MMA chain instead of forming one big serial epilogue.
__device__ __forceinline__ void layer_fused(
    const uint4* __restrict__ w4, int lane, int lz, int tig, bool primal, float ph,
    const float* __restrict__ bias, float s, bool residual,
    const uint32_t* __restrict__ Ain_h, const uint32_t* __restrict__ Ain_l,
    uint32_t* __restrict__ Out_h, uint32_t* __restrict__ Out_l)
{
    const float OmS = OMEGA * s;
#pragma unroll
    for (int nt = 0; nt < 16; nt++) {
        float4 a = make_float4(0.f, 0.f, 0.f, 0.f);
#pragma unroll
        for (int ks = 0; ks < 8; ks++) {
            uint4 bb = w4[(nt * 8 + ks) * 32 + lane];
            mma16816(a, Ain_h + 4 * ks, bb.x, bb.y);   // hi * Whi
            mma16816(a, Ain_l + 4 * ks, bb.x, bb.y);   // lo * Whi
            mma16816(a, Ain_h + 4 * ks, bb.z, bb.w);   // hi * Wlo
        }
        const int n0 = 8 * nt + 2 * tig;
        float ob0 = fmaf(OMEGA, bias[n0], ph);
        float ob1 = fmaf(OMEGA, bias[n0 + 1], ph);
        float z0 = __shfl_sync(0xffffffffu, a.x, lz);
        float z1 = __shfl_sync(0xffffffffu, a.y, lz);
        float z2 = __shfl_sync(0xffffffffu, a.z, lz);
        float z3 = __shfl_sync(0xffffffffu, a.w, lz);
        float v0 = __sinf(fmaf(OmS, z0, ob0));
        float v1 = __sinf(fmaf(OmS, z1, ob1));
        float v2 = __sinf(fmaf(OmS, z2, ob0));
        float v3 = __sinf(fmaf(OmS, z3, ob1));
        float e0 = primal ? v0 : OmS * v0 * a.x;
        float e1 = primal ? v1 : OmS * v1 * a.y;
        float e2 = primal ? v2 : OmS * v2 * a.z;
        float e3 = primal ? v3 : OmS * v3 * a.w;
        if (residual) {
            float2 p0 = upk2(Out_h[2 * nt], Out_l[2 * nt]);
            float2 p1 = upk2(Out_h[2 * nt + 1], Out_l[2 * nt + 1]);
            e0 += p0.x; e1 += p0.y; e2 += p1.x; e3 += p1.y;
        }
        split2(e0, e1, Out_h[2 * nt],     Out_l[2 * nt]);
        split2(e2, e3, Out_h[2 * nt + 1], Out_l[2 * nt + 1]);
    }
}

// ---------------- main kernel ----------------
__global__ void __launch_bounds__(256, 1)
fsrn_mma(const float* __restrict__ coords,
         const float* __restrict__ first_w, const float* __restrict__ first_b,
         const float* __restrict__ res_b1,  const float* __restrict__ res_b2,
         const float* __restrict__ final_w, float* __restrict__ out) {
    extern __shared__ unsigned char smem[];
    const uint32_t sb = smem_u32(smem);
    const int tid = threadIdx.x, w = tid >> 5, lane = tid & 31;
    const int gr = lane >> 2, tig = lane & 3;
    const int lz = lane & ~12;            // lane holding the primal-row acc
    const int r0 = w * 16 + gr;           // rows r0 and r0+8
    const int ch = r0 & 3;
    const int pt0 = r0 >> 2, pt1 = (r0 + 8) >> 2;
    const bool primal = (ch == 0);
    const float ph = primal ? 0.0f : PIO2;

    const uint32_t mbr0 = sb + SM_MBAR_R0, mbr1 = sb + SM_MBAR_R1;
    const uint32_t mbf0 = sb + SM_MBAR_F0, mbf1 = sb + SM_MBAR_F1;
    if (tid == 0) {
        mbar_init(mbr0, 1); mbar_init(mbr1, 1);
        mbar_init(mbf0, 8); mbar_init(mbf1, 8);
    }
    __syncthreads();
    if (tid == 0) {
        mbar_expect(mbr0, 65536); bulk_g2s(sb + SM_W0, g_wfrag,        65536, mbr0);
        mbar_expect(mbr1, 65536); bulk_g2s(sb + SM_W1, g_wfrag + 4096, 65536, mbr1);
    }

    // ---- stage constants
    float* cs = (float*)(smem + SM_CONST);
    for (int i = tid; i < 1792; i += 256) {
        float v;
        if (i < 128)       v = first_b[i];
        else if (i < 512)  { int idx = i - 128; v = first_w[(idx & 127) * 3 + (idx >> 7)]; }
        else if (i < 896)  v = res_b1[i - 512];
        else if (i < 1280) v = res_b2[i - 896];
        else               v = final_w[i - 1280];
        cs[i] = v;
    }
    __syncthreads();
    const float* fb_s  = cs;
    const float* fwT   = cs + 128;     // [k*128 + n]
    const float* rb1_s = cs + 512;
    const float* rb2_s = cs + 896;
    const float* fwf   = cs + 1280;    // [jo*128 + n]

    uint32_t Sh[32], Sl[32], Ah[32], Al[32];

    // ---- first layer (registers only)
    {
        int gp0 = blockIdx.x * 32 + pt0, gp1 = blockIdx.x * 32 + pt1;
        float c0x = coords[gp0 * 3], c0y = coords[gp0 * 3 + 1], c0z = coords[gp0 * 3 + 2];
        float c1x = coords[gp1 * 3], c1y = coords[gp1 * 3 + 1], c1z = coords[gp1 * 3 + 2];
        const float* fsel = fwT + (primal ? 0 : (ch - 1)) * 128;
#pragma unroll
        for (int nt = 0; nt < 16; nt++) {
            int n0 = 8 * nt + 2 * tig;
            float e0[2], e1[2];
#pragma unroll
            for (int q = 0; q < 2; q++) {
                int n = n0 + q;
                float f0 = fwT[n], f1 = fwT[128 + n], f2 = fwT[256 + n], fb = fb_s[n];
                float zb0 = fmaf(f0, c0x, fmaf(f1, c0y, fmaf(f2, c0z, fb)));
                float zb1 = fmaf(f0, c1x, fmaf(f1, c1y, fmaf(f2, c1z, fb)));
                float fac = primal ? 1.0f : OMEGA * fsel[n];
                e0[q] = __sinf(fmaf(OMEGA, zb0, ph)) * fac;
                e1[q] = __sinf(fmaf(OMEGA, zb1, ph)) * fac;
            }
            split2(e0[0], e0[1], Sh[2 * nt],     Sl[2 * nt]);
            split2(e1[0], e1[1], Sh[2 * nt + 1], Sl[2 * nt + 1]);
        }
    }

    const uint4* w40 = (const uint4*)(smem + SM_W0);
    const uint4* w41 = (const uint4*)(smem + SM_W1);

    // ---- 3 residual blocks (2 layers each); ready mbarriers gate weight
    // consumption, free mbarriers (8 warp arrivals) gate re-prefetch.
    for (int b = 0; b < 3; b++) {
        const float s = (b == 0) ? 1.0f : 0.5f;

        // ===== layer 2b (w1): A = S -> B1 in Ah/Al, weights in W0
        mbar_wait(mbr0, b & 1);
        layer_fused(w40, lane, lz, tig, primal, ph,
                    rb1_s + b * 128, s, false, Sh, Sl, Ah, Al);
        if (lane == 0) mbar_arrive(mbf0);
        if (tid == 0 && b < 2) {       // refill W0 with layer 2b+2
            mbar_wait(mbf0, b);
            mbar_expect(mbr0, 65536);
            bulk_g2s(sb + SM_W0, g_wfrag + (2 * b + 2) * 4096, 65536, mbr0);
        }

        // ===== layer 2b+1 (w2): A = B1 -> S += ..., weights in W1
        mbar_wait(mbr1, b & 1);
        layer_fused(w41, lane, lz, tig, primal, ph,
                    rb2_s + b * 128, 1.0f, true, Ah, Al, Sh, Sl);
        if (lane == 0) mbar_arrive(mbf1);
        if (tid == 0 && b < 2) {       // refill W1 with layer 2b+3
            mbar_wait(mbf1, b);
            mbar_expect(mbr1, 65536);
            bulk_g2s(sb + SM_W1, g_wfrag + (2 * b + 3) * 4096, 65536, mbr1);
        }
    }

    // ---- final layer: J[p][jo][k] = final_w[jo] . dh_k[p] (tangent rows only)
    float J0[4] = {0.f, 0.f, 0.f, 0.f};
    float J1[4] = {0.f, 0.f, 0.f, 0.f};
#pragma unroll
    for (int nt = 0; nt < 16; nt++) {
        int n0 = 8 * nt + 2 * tig;
        float2 p0 = upk2(Sh[2 * nt],     Sl[2 * nt]);
        float2 p1 = upk2(Sh[2 * nt + 1], Sl[2 * nt + 1]);
#pragma unroll
        for (int jo = 0; jo < 4; jo++) {
            float f0 = fwf[jo * 128 + n0], f1 = fwf[jo * 128 + n0 + 1];
            J0[jo] = fmaf(f0, p0.x, fmaf(f1, p0.y, J0[jo]));
            J1[jo] = fmaf(f0, p1.x, fmaf(f1, p1.y, J1[jo]));
        }
    }
#pragma unroll
    for (int off = 1; off <= 2; off <<= 1) {
#pragma unroll
        for (int jo = 0; jo < 4; jo++) {
            J0[jo] += __shfl_xor_sync(0xffffffffu, J0[jo], off);
            J1[jo] += __shfl_xor_sync(0xffffffffu, J1[jo], off);
        }
    }
    float* Jsh = (float*)(smem + SM_J);
    if (tig == 0 && ch != 0) {
#pragma unroll
        for (int jo = 0; jo < 4; jo++) {
            Jsh[pt0 * 12 + jo * 3 + (ch - 1)] = J0[jo];
            Jsh[pt1 * 12 + jo * 3 + (ch - 1)] = J1[jo];
        }
    }
    __syncthreads();

    if (tid < 32) {
        const float* Jp = Jsh + tid * 12;          // [jo*3 + k]
        int gp = blockIdx.x * 32 + tid;
        out[gp * 3 + 0] = Jp[0] + Jp[10] - Jp[8];  // J00 + J31 - J22
        out[gp * 3 + 1] = Jp[1] + Jp[5]  - Jp[9];  // J01 + J12 - J30
        out[gp * 3 + 2] = Jp[2] + Jp[6]  - Jp[4];  // J02 + J20 - J11
    }
}

extern "C" void kernel_launch(void* const* d_in, const int* in_sizes, int n_in,
                              void* d_out, int out_size) {
    const float* coords  = (const float*)d_in[0];
    const float* first_w = (const float*)d_in[1];
    const float* first_b = (const float*)d_in[2];
    const float* res_w1  = (const float*)d_in[3];
    const float* res_b1  = (const float*)d_in[4];
    const float* res_w2  = (const float*)d_in[5];
    const float* res_b2  = (const float*)d_in[6];
    const float* final_w = (const float*)d_in[7];
    // final_b (d_in[8]) drops out of the jacobian — unused.

    int n = in_sizes[0] / 3;

    prep_kernel<<<(6 * 4096 + 255) / 256, 256>>>(res_w1, res_w2);

    cudaFuncSetAttribute(fsrn_mma, cudaFuncAttributeMaxDynamicSharedMemorySize, SM_TOTAL);
    fsrn_mma<<<n / 32, 256, SM_TOTAL>>>(coords, first_w, first_b,
                                        res_b1, res_b2, final_w, (float*)d_out);
}